// round 8
// baseline (speedup 1.0000x reference)
#include <cuda_runtime.h>

// ---------------------------------------------------------------------------
// DeepESN on B200 (sm_100a), round 8.
//   drive GEMM  u = X @ Win + b  (parallel, f32x2-packed)   [unchanged]
//   recurrence  h' = 0.1 h + 0.9 tanh(u_t + h @ Wrec)
//     128 CTAs = 16 batch-groups (16 rows) x 8 col-slices (64 cols)
//     NEW: 512 threads (16 warps = 2 rowgroups x 8 k-chunks of 64)
//     NEW: cluster(8) hardware barrier (release-arrive / acquire-wait)
//     NEW: u prefetched before the cluster wait (latency hidden)
//     Wrec slice (64 x 512) SMEM-resident for all 512 steps.
// ---------------------------------------------------------------------------

#define BB   256
#define TT   512
#define UU   512
#define NCLS 10

// recurrence tiling
#define NGRP 16        // batch groups
#define BCR  16        // rows per group
#define NSLC 8         // col slices (= cluster size)
#define NCOL 64        // cols per slice
#define SSTR 516       // padded k stride (512 + 4)
#define RPAD 66        // padded out-stride of reduction planes
#define NTR  512       // threads per recur CTA (16 warps)
#define NT   256       // threads for gemm/init/readout

// drive GEMM tiling
#define ASTR 130
#define BSTR 68

// device scratch (allocation forbidden; __device__ globals are the path)
__device__ float g_S0[(size_t)BB * TT * UU];
__device__ float g_S1[(size_t)BB * TT * UU];
__device__ float g_U [(size_t)BB * TT * UU];
__device__ float g_H[2][BB * UU];
__device__ float g_R[BB * 3 * UU];

__device__ __forceinline__ void dfma2(unsigned long long& d,
                                      unsigned long long a,
                                      unsigned long long b) {
    asm("fma.rn.f32x2 %0, %1, %2, %0;" : "+l"(d) : "l"(a), "l"(b));
}
__device__ __forceinline__ float dsum2(unsigned long long v) {
    float lo, hi;
    asm("mov.b64 {%0, %1}, %2;" : "=f"(lo), "=f"(hi) : "l"(v));
    return lo + hi;
}
__device__ __forceinline__ unsigned long long pk2(float x) {
    unsigned long long r;
    asm("mov.b64 %0, {%1, %1};" : "=l"(r) : "f"(x));
    return r;
}
__device__ __forceinline__ void upk2(unsigned long long v, float& lo, float& hi) {
    asm("mov.b64 {%0, %1}, %2;" : "=f"(lo), "=f"(hi) : "l"(v));
}

// ============================================================================
// Drive GEMM: g_U[M,512] = A[M,K] @ W[K,512] + bias.  M = BB*TT, K in {64,512}.
// A selected in-kernel: layer 0 -> x (arg), layer 1 -> g_S0, layer 2 -> g_S1.
// ============================================================================
__global__ void __launch_bounds__(NT)
drive_gemm(const float* __restrict__ x, const float* __restrict__ W,
           const float* __restrict__ bias, int K, int layer)
{
    __shared__ float As[16 * ASTR];   // transposed: As[k][row]
    __shared__ float Bs[16 * BSTR];   // Bs[k][col]

    const float* A = (layer == 0) ? x : ((layer == 1) ? g_S0 : g_S1);
    float*       C = g_U;

    const int tid = threadIdx.x;
    const int tx  = tid & 15;
    const int ty  = tid >> 4;
    const int m0  = blockIdx.y * 128;
    const int n0  = blockIdx.x * 64;

    unsigned long long acc[4][4];
#pragma unroll
    for (int p = 0; p < 4; ++p)
#pragma unroll
        for (int c = 0; c < 4; ++c) acc[p][c] = 0ull;

    for (int kt = 0; kt < K; kt += 16) {
#pragma unroll
        for (int it = 0; it < 2; ++it) {
            int idx = tid + it * NT;
            int row = idx >> 2, c4 = idx & 3;
            float4 v = __ldg(reinterpret_cast<const float4*>(
                                 A + (size_t)(m0 + row) * K + kt) + c4);
            As[(c4 * 4 + 0) * ASTR + row] = v.x;
            As[(c4 * 4 + 1) * ASTR + row] = v.y;
            As[(c4 * 4 + 2) * ASTR + row] = v.z;
            As[(c4 * 4 + 3) * ASTR + row] = v.w;
        }
        {
            int k = tid >> 4, c4 = tid & 15;
            float4 v = __ldg(reinterpret_cast<const float4*>(
                                 W + (size_t)(kt + k) * UU + n0) + c4);
            *reinterpret_cast<float4*>(Bs + k * BSTR + c4 * 4) = v;
        }
        __syncthreads();

#pragma unroll
        for (int k = 0; k < 16; ++k) {
            unsigned long long a[4];
#pragma unroll
            for (int p = 0; p < 4; ++p)
                a[p] = *reinterpret_cast<const unsigned long long*>(
                           As + k * ASTR + ty * 8 + 2 * p);
            float4 b = *reinterpret_cast<const float4*>(Bs + k * BSTR + tx * 4);
            unsigned long long bb[4] = {pk2(b.x), pk2(b.y), pk2(b.z), pk2(b.w)};
#pragma unroll
            for (int p = 0; p < 4; ++p) {
                dfma2(acc[p][0], a[p], bb[0]);
                dfma2(acc[p][1], a[p], bb[1]);
                dfma2(acc[p][2], a[p], bb[2]);
                dfma2(acc[p][3], a[p], bb[3]);
            }
        }
        __syncthreads();
    }

    float4 bv = __ldg(reinterpret_cast<const float4*>(bias + n0 + tx * 4));
#pragma unroll
    for (int p = 0; p < 4; ++p) {
        float4 lo, hi;
        upk2(acc[p][0], lo.x, hi.x);
        upk2(acc[p][1], lo.y, hi.y);
        upk2(acc[p][2], lo.z, hi.z);
        upk2(acc[p][3], lo.w, hi.w);
        lo.x += bv.x; lo.y += bv.y; lo.z += bv.z; lo.w += bv.w;
        hi.x += bv.x; hi.y += bv.y; hi.z += bv.z; hi.w += bv.w;
        size_t r0 = (size_t)(m0 + ty * 8 + 2 * p) * UU + n0 + tx * 4;
        *reinterpret_cast<float4*>(C + r0)      = lo;
        *reinterpret_cast<float4*>(C + r0 + UU) = hi;
    }
}

// ============================================================================
// Recurrence kernel. 16 warps: (rowgroup rg in {0,1}) x (k-chunk kc in 0..7).
// Lane j covers cols (j, j+32) packed over k-pairs; 8 rows of its rowgroup.
// Cross-CTA sync: hardware cluster barrier over the 8 col-slice CTAs.
// ============================================================================
__global__ void __launch_bounds__(NTR, 1) __cluster_dims__(NSLC, 1, 1)
recur_kernel(const float* __restrict__ Wrec, int layer)
{
    extern __shared__ float smem[];
    float* sWT  = smem;                       // [64][SSTR] transposed Wrec slice
    float* sSt  = smem + NCOL * SSTR;         // [16][SSTR] staged H rows
    float* sRed = sSt + BCR * SSTR;           // [8*16 planes][RPAD] partials

    const float* u    = g_U;
    float*       sout = (layer == 0) ? g_S0 : ((layer == 1) ? g_S1 : (float*)0);

    const int tid  = threadIdx.x;
    const int lane = tid & 31;
    const int wid  = tid >> 5;                // 0..15
    const int rg   = wid & 1;                 // rowgroup: rows rg*8..rg*8+7
    const int kc   = wid >> 1;                // k chunk: [kc*64, kc*64+64)
    const int bid  = blockIdx.x;
    const int grp  = bid >> 3;                // batch group (cluster id)
    const int sl   = bid & 7;                 // col slice (cluster rank)
    const int b0   = grp * BCR;
    const int col0 = sl * NCOL;
    const int kbase = kc * 64;
    (void)sl;

    // finalize ownership: thread -> 2 adjacent outputs (row fi, cols fc, fc+1)
    const int fo  = tid * 2;
    const int fi  = fo >> 6;                  // row 0..15
    const int fc  = fo & 63;                  // even col base
    const int fr  = fi & 7;
    const int frg = fi >> 3;
    const int fj  = fc & 31;
    const int fcc = fc >> 5;                  // same for fc and fc+1 (fc even)

    // Load transposed weight slice: sWT[c][k] = Wrec[k][col0+c]
    for (int idx = tid; idx < NCOL * UU; idx += NTR) {
        int c = idx & 63, k = idx >> 6;
        sWT[c * SSTR + k] = Wrec[(size_t)k * UU + col0 + c];
    }
    __syncthreads();

    for (int t = 0; t < TT; ++t) {
        const int p = t & 1;

        // prefetch this step's u (issued before the cluster wait -> hidden)
        const size_t m = (size_t)(b0 + fi) * TT + t;
        const float2 uv = __ldg(reinterpret_cast<const float2*>(
                                    u + m * UU + col0 + fc));

        // cluster wait doubles as a full intra-CTA barrier (all threads arrive)
        if (t > 0)
            asm volatile("barrier.cluster.wait.aligned;" ::: "memory");

        // stage H[p] rows [16 x 512]; L2 reads (L1 may be stale across steps)
        for (int idx = tid; idx < BCR * 128; idx += NTR) {
            int i = idx >> 7, c = idx & 127;
            float4 v = __ldcg(reinterpret_cast<const float4*>(
                                  g_H[p] + (size_t)(b0 + i) * UU) + c);
            reinterpret_cast<float4*>(sSt + i * SSTR)[c] = v;
        }
        __syncthreads();

        unsigned long long acc[8][2];
#pragma unroll
        for (int r = 0; r < 8; ++r) { acc[r][0] = 0ull; acc[r][1] = 0ull; }

        const ulonglong2* w0p = reinterpret_cast<const ulonglong2*>(
            sWT + lane * SSTR + kbase);
        const ulonglong2* w1p = reinterpret_cast<const ulonglong2*>(
            sWT + (lane + 32) * SSTR + kbase);
        const float* arow = sSt + rg * 8 * SSTR + kbase;

#pragma unroll 2
        for (int c = 0; c < 16; ++c) {
            ulonglong2 w0 = w0p[c];
            ulonglong2 w1 = w1p[c];
#pragma unroll
            for (int r = 0; r < 8; ++r) {
                ulonglong2 a = *reinterpret_cast<const ulonglong2*>(
                    arow + r * SSTR + 4 * c);
                dfma2(acc[r][0], a.x, w0.x);
                dfma2(acc[r][0], a.y, w0.y);
                dfma2(acc[r][1], a.x, w1.x);
                dfma2(acc[r][1], a.y, w1.y);
            }
        }

        // partials: plane = kc*16 + (r*2+cc), out = rg*32+lane (stride-1: no
        // bank conflicts)
        {
            float* base = sRed + (size_t)(kc * 16) * RPAD + rg * 32 + lane;
#pragma unroll
            for (int r = 0; r < 8; ++r) {
                base[(r * 2 + 0) * RPAD] = dsum2(acc[r][0]);
                base[(r * 2 + 1) * RPAD] = dsum2(acc[r][1]);
            }
        }
        __syncthreads();

        // finalize 2 outputs per thread
        {
            float2 hold = *reinterpret_cast<const float2*>(
                sSt + fi * SSTR + col0 + fc);
            float z0 = uv.x, z1 = uv.y;
            const float* rb = sRed + (size_t)(fr * 2 + fcc) * RPAD
                                   + frg * 32 + fj;
#pragma unroll
            for (int k2 = 0; k2 < 8; ++k2) {
                float2 pv = *reinterpret_cast<const float2*>(
                    rb + (size_t)k2 * 16 * RPAD);
                z0 += pv.x; z1 += pv.y;
            }
            float2 hn;
            hn.x = hold.x * 0.1f + 0.9f * tanhf(z0);
            hn.y = hold.y * 0.1f + 0.9f * tanhf(z1);
            size_t gh = (size_t)(b0 + fi) * UU + col0 + fc;
            *reinterpret_cast<float2*>(g_H[p ^ 1] + gh) = hn;
            if (sout)
                *reinterpret_cast<float2*>(sout + m * UU + col0 + fc) = hn;
            if (t == TT - 1)
                *reinterpret_cast<float2*>(
                    g_R + (size_t)(b0 + fi) * (3 * UU) + layer * UU
                        + col0 + fc) = hn;
        }

        // release-arrive: orders the h stores for peers' acquire-wait
        if (t < TT - 1)
            asm volatile("barrier.cluster.arrive.aligned;" ::: "memory");
    }
}

__global__ void init_kernel() {
    int idx = blockIdx.x * blockDim.x + threadIdx.x;
    if (idx < 2 * BB * UU) ((float*)g_H)[idx] = 0.0f;
}

__global__ void readout_kernel(const float* __restrict__ Wout,
                               const float* __restrict__ bout,
                               float* __restrict__ out) {
    __shared__ float red[NCLS][NT];
    int b = blockIdx.x, tid = threadIdx.x;
    float part[NCLS];
#pragma unroll
    for (int c = 0; c < NCLS; ++c) part[c] = 0.0f;
    for (int k = tid; k < 3 * UU; k += NT) {
        float r = g_R[(size_t)b * 3 * UU + k];
#pragma unroll
        for (int c = 0; c < NCLS; ++c) part[c] += r * Wout[k * NCLS + c];
    }
#pragma unroll
    for (int c = 0; c < NCLS; ++c) red[c][tid] = part[c];
    __syncthreads();
    if (tid < NCLS) {
        float s = 0.0f;
        for (int i = 0; i < NT; ++i) s += red[tid][i];
        out[b * NCLS + tid] = s + bout[tid];
    }
}

extern "C" void kernel_launch(void* const* d_in, const int* in_sizes, int n_in,
                              void* d_out, int out_size) {
    (void)in_sizes; (void)n_in; (void)out_size;
    const float* x    = (const float*)d_in[0];
    const float* Win0 = (const float*)d_in[1];
    const float* W0   = (const float*)d_in[2];
    const float* b0   = (const float*)d_in[3];
    const float* Win1 = (const float*)d_in[4];
    const float* W1   = (const float*)d_in[5];
    const float* b1   = (const float*)d_in[6];
    const float* Win2 = (const float*)d_in[7];
    const float* W2   = (const float*)d_in[8];
    const float* b2   = (const float*)d_in[9];
    const float* Wout = (const float*)d_in[10];
    const float* bout = (const float*)d_in[11];
    float* out = (float*)d_out;

    // smem: weights 64x516 + stage 16x516 + red 128x66 = 198,912 B
    const int smem = (NCOL * SSTR + BCR * SSTR + 128 * RPAD) * (int)sizeof(float);
    static int attr_done = 0;           // first call is uncaptured; replays skip
    if (!attr_done) {
        cudaFuncSetAttribute(recur_kernel,
                             cudaFuncAttributeMaxDynamicSharedMemorySize, smem);
        attr_done = 1;
    }

    const dim3 gemm_grid(UU / 64, (BB * TT) / 128);

    // layer 0
    init_kernel<<<1024, NT>>>();
    drive_gemm<<<gemm_grid, NT>>>(x, Win0, b0, 64, 0);
    recur_kernel<<<NGRP * NSLC, NTR, smem>>>(W0, 0);

    // layer 1
    init_kernel<<<1024, NT>>>();
    drive_gemm<<<gemm_grid, NT>>>(x, Win1, b1, 512, 1);
    recur_kernel<<<NGRP * NSLC, NTR, smem>>>(W1, 1);

    // layer 2
    init_kernel<<<1024, NT>>>();
    drive_gemm<<<gemm_grid, NT>>>(x, Win2, b2, 512, 2);
    recur_kernel<<<NGRP * NSLC, NTR, smem>>>(W2, 2);

    readout_kernel<<<BB, NT>>>(Wout, bout, out);
}

// round 10
// speedup vs baseline: 1.5929x; 1.5929x over previous
#include <cuda_runtime.h>

// ---------------------------------------------------------------------------
// DeepESN on B200 (sm_100a), round 10 (= round-9 source, resubmitted after an
// infra-level container failure; R4->R5 precedent: identical resubmits pass).
//   drive GEMM  u = X @ Win + b  (parallel, f32x2-packed)
//   recurrence  h' = 0.1 h + 0.9 tanh(u_t + h @ Wrec)
//     128 CTAs = 16 batch-groups (16 rows) x 8 col-slices (64 cols)
//     512 threads = 16 warps = 16 k-chunks of 32; lane = 2 cols x 16 rows
//       -> each weight LDS.128 feeds 16 rows: FMA-bound (4096 cyc/step floor)
//     Reduction planes [kc][row][slot] float2, aliased over the H stage.
//     Cross-CTA sync: monotonic atomic barrier (CG grid-sync pattern),
//     fence by tid0 only; u prefetched before the spin.
// ---------------------------------------------------------------------------

#define BB   256
#define TT   512
#define UU   512
#define NCLS 10

// recurrence tiling
#define NGRP 16        // batch groups
#define BCR  16        // rows per group
#define NSLC 8         // col slices per group
#define NCOL 64        // cols per slice
#define SSTR 516       // padded k stride (512 + 4): 4 mod 32 -> conflict-free
#define RSTR 66        // reduction row stride (slots, padded)
#define KCN  16        // k-chunks (= warps)
#define NTR  512       // threads per recur CTA
#define NT   256       // threads for gemm/init/readout

// drive GEMM tiling
#define ASTR 130
#define BSTR 68

// device scratch (allocation forbidden; __device__ globals are the path)
__device__ float        g_S0[(size_t)BB * TT * UU];
__device__ float        g_S1[(size_t)BB * TT * UU];
__device__ float        g_U [(size_t)BB * TT * UU];
__device__ float        g_H[2][BB * UU];
__device__ float        g_R[BB * 3 * UU];
__device__ unsigned int g_bar[NGRP];

__device__ __forceinline__ void dfma2(unsigned long long& d,
                                      unsigned long long a,
                                      unsigned long long b) {
    asm("fma.rn.f32x2 %0, %1, %2, %0;" : "+l"(d) : "l"(a), "l"(b));
}
__device__ __forceinline__ float dsum2(unsigned long long v) {
    float lo, hi;
    asm("mov.b64 {%0, %1}, %2;" : "=f"(lo), "=f"(hi) : "l"(v));
    return lo + hi;
}
__device__ __forceinline__ unsigned long long pk2(float x) {
    unsigned long long r;
    asm("mov.b64 %0, {%1, %1};" : "=l"(r) : "f"(x));
    return r;
}
__device__ __forceinline__ void upk2(unsigned long long v, float& lo, float& hi) {
    asm("mov.b64 {%0, %1}, %2;" : "=f"(lo), "=f"(hi) : "l"(v));
}

// ============================================================================
// Drive GEMM: g_U[M,512] = A[M,K] @ W[K,512] + bias.  M = BB*TT, K in {64,512}.
// A selected in-kernel: layer 0 -> x (arg), layer 1 -> g_S0, layer 2 -> g_S1.
// ============================================================================
__global__ void __launch_bounds__(NT)
drive_gemm(const float* __restrict__ x, const float* __restrict__ W,
           const float* __restrict__ bias, int K, int layer)
{
    __shared__ float As[16 * ASTR];   // transposed: As[k][row]
    __shared__ float Bs[16 * BSTR];   // Bs[k][col]

    const float* A = (layer == 0) ? x : ((layer == 1) ? g_S0 : g_S1);
    float*       C = g_U;

    const int tid = threadIdx.x;
    const int tx  = tid & 15;
    const int ty  = tid >> 4;
    const int m0  = blockIdx.y * 128;
    const int n0  = blockIdx.x * 64;

    unsigned long long acc[4][4];
#pragma unroll
    for (int p = 0; p < 4; ++p)
#pragma unroll
        for (int c = 0; c < 4; ++c) acc[p][c] = 0ull;

    for (int kt = 0; kt < K; kt += 16) {
#pragma unroll
        for (int it = 0; it < 2; ++it) {
            int idx = tid + it * NT;
            int row = idx >> 2, c4 = idx & 3;
            float4 v = __ldg(reinterpret_cast<const float4*>(
                                 A + (size_t)(m0 + row) * K + kt) + c4);
            As[(c4 * 4 + 0) * ASTR + row] = v.x;
            As[(c4 * 4 + 1) * ASTR + row] = v.y;
            As[(c4 * 4 + 2) * ASTR + row] = v.z;
            As[(c4 * 4 + 3) * ASTR + row] = v.w;
        }
        {
            int k = tid >> 4, c4 = tid & 15;
            float4 v = __ldg(reinterpret_cast<const float4*>(
                                 W + (size_t)(kt + k) * UU + n0) + c4);
            *reinterpret_cast<float4*>(Bs + k * BSTR + c4 * 4) = v;
        }
        __syncthreads();

#pragma unroll
        for (int k = 0; k < 16; ++k) {
            unsigned long long a[4];
#pragma unroll
            for (int p = 0; p < 4; ++p)
                a[p] = *reinterpret_cast<const unsigned long long*>(
                           As + k * ASTR + ty * 8 + 2 * p);
            float4 b = *reinterpret_cast<const float4*>(Bs + k * BSTR + tx * 4);
            unsigned long long bb[4] = {pk2(b.x), pk2(b.y), pk2(b.z), pk2(b.w)};
#pragma unroll
            for (int p = 0; p < 4; ++p) {
                dfma2(acc[p][0], a[p], bb[0]);
                dfma2(acc[p][1], a[p], bb[1]);
                dfma2(acc[p][2], a[p], bb[2]);
                dfma2(acc[p][3], a[p], bb[3]);
            }
        }
        __syncthreads();
    }

    float4 bv = __ldg(reinterpret_cast<const float4*>(bias + n0 + tx * 4));
#pragma unroll
    for (int p = 0; p < 4; ++p) {
        float4 lo, hi;
        upk2(acc[p][0], lo.x, hi.x);
        upk2(acc[p][1], lo.y, hi.y);
        upk2(acc[p][2], lo.z, hi.z);
        upk2(acc[p][3], lo.w, hi.w);
        lo.x += bv.x; lo.y += bv.y; lo.z += bv.z; lo.w += bv.w;
        hi.x += bv.x; hi.y += bv.y; hi.z += bv.z; hi.w += bv.w;
        size_t r0 = (size_t)(m0 + ty * 8 + 2 * p) * UU + n0 + tx * 4;
        *reinterpret_cast<float4*>(C + r0)      = lo;
        *reinterpret_cast<float4*>(C + r0 + UU) = hi;
    }
}

// ============================================================================
// Recurrence kernel. 16 warps = 16 k-chunks of 32 k-values.
// Lane j: cols (col0+j, col0+j+32), ALL 16 rows (weight reuse x16).
// Finalize: thread (fi = tid>>5, fj = lane) owns cols (fj, fj+32) of row fi.
// ============================================================================
__global__ void __launch_bounds__(NTR, 1)
recur_kernel(const float* __restrict__ Wrec, int layer)
{
    extern __shared__ float smem[];
    float* sWT  = smem;                       // [64][SSTR] transposed Wrec slice
    float* sSt  = smem + NCOL * SSTR;         // [16][SSTR] staged H rows
    float* sRed = sSt;                        // ALIAS: [16 kc][16 r][RSTR] f2 slots

    const float* u    = g_U;
    float*       sout = (layer == 0) ? g_S0 : ((layer == 1) ? g_S1 : (float*)0);

    const int tid  = threadIdx.x;
    const int lane = tid & 31;
    const int kc   = tid >> 5;                // warp = k-chunk 0..15
    const int bid  = blockIdx.x;
    const int grp  = bid >> 3;                // batch group
    const int sl   = bid & 7;                 // col slice
    const int b0   = grp * BCR;
    const int col0 = sl * NCOL;
    const int kbase = kc * 32;

    const int fi = tid >> 5;                  // finalize row (== kc)
    const int fj = lane;                      // finalize col pair (fj, fj+32)

    // Load transposed weight slice: sWT[c][k] = Wrec[k][col0+c]
    for (int idx = tid; idx < NCOL * UU; idx += NTR) {
        int c = idx & 63, k = idx >> 6;
        sWT[c * SSTR + k] = Wrec[(size_t)k * UU + col0 + c];
    }
    __syncthreads();

    unsigned int tgt = 0;

    for (int t = 0; t < TT; ++t) {
        const int p = t & 1;
        const size_t m = (size_t)(b0 + fi) * TT + t;

        // prefetch this step's u (u is constant during this launch)
        const float u0 = __ldg(u + m * UU + col0 + fj);
        const float u1 = __ldg(u + m * UU + col0 + fj + 32);

        // ---- wait phase (peers' step t-1 h stores must be visible) ----
        if (t > 0) {
            if (tid == 0) {
                unsigned int v;
                do {
                    asm volatile("ld.acquire.gpu.u32 %0, [%1];"
                                 : "=r"(v) : "l"(&g_bar[grp]));
                    if (v >= tgt) break;
                    __nanosleep(32);
                } while (true);
            }
            __syncthreads();
        }

        // ---- stage H[p] rows [16 x 512] (L2 reads; L1 stale across steps) ----
        for (int idx = tid; idx < BCR * 128; idx += NTR) {
            int i = idx >> 7, c = idx & 127;
            float4 v = __ldcg(reinterpret_cast<const float4*>(
                                  g_H[p] + (size_t)(b0 + i) * UU) + c);
            reinterpret_cast<float4*>(sSt + i * SSTR)[c] = v;
        }
        __syncthreads();

        // ---- matmul: acc[r][cc] += sum_{k in chunk} H[r][k] * W[k][col] ----
        unsigned long long acc[16][2];
#pragma unroll
        for (int r = 0; r < 16; ++r) { acc[r][0] = 0ull; acc[r][1] = 0ull; }

        const ulonglong2* w0p = reinterpret_cast<const ulonglong2*>(
            sWT + lane * SSTR + kbase);
        const ulonglong2* w1p = reinterpret_cast<const ulonglong2*>(
            sWT + (lane + 32) * SSTR + kbase);
        const float* abase = sSt + kbase;

#pragma unroll 2
        for (int c = 0; c < 8; ++c) {
            ulonglong2 w0 = w0p[c];
            ulonglong2 w1 = w1p[c];
#pragma unroll
            for (int r = 0; r < 16; ++r) {
                ulonglong2 a = *reinterpret_cast<const ulonglong2*>(
                    abase + r * SSTR + 4 * c);
                dfma2(acc[r][0], a.x, w0.x);
                dfma2(acc[r][0], a.y, w0.y);
                dfma2(acc[r][1], a.x, w1.x);
                dfma2(acc[r][1], a.y, w1.y);
            }
        }

        // read hold BEFORE sRed overwrites the stage (alias)
        const float hold0 = sSt[fi * SSTR + col0 + fj];
        const float hold1 = sSt[fi * SSTR + col0 + fj + 32];
        __syncthreads();

        // ---- write partials: [kc][r][lane*2] = {col j, col j+32} ----
        {
            float* base = sRed + (size_t)kc * (16 * RSTR) + lane * 2;
#pragma unroll
            for (int r = 0; r < 16; ++r) {
                float2 v;
                v.x = dsum2(acc[r][0]);
                v.y = dsum2(acc[r][1]);
                *reinterpret_cast<float2*>(base + r * RSTR) = v;
            }
        }
        __syncthreads();

        // ---- finalize: sum 16 chunk-partials, tanh, store ----
        {
            float z0 = u0, z1 = u1;
            const float* rb = sRed + (size_t)fi * RSTR + fj * 2;
#pragma unroll
            for (int k2 = 0; k2 < KCN; ++k2) {
                float2 pv = *reinterpret_cast<const float2*>(
                    rb + (size_t)k2 * (16 * RSTR));
                z0 += pv.x; z1 += pv.y;
            }
            float hn0 = hold0 * 0.1f + 0.9f * tanhf(z0);
            float hn1 = hold1 * 0.1f + 0.9f * tanhf(z1);
            size_t gh = (size_t)(b0 + fi) * UU + col0 + fj;
            g_H[p ^ 1][gh]      = hn0;
            g_H[p ^ 1][gh + 32] = hn1;
            if (sout) {
                sout[m * UU + col0 + fj]      = hn0;
                sout[m * UU + col0 + fj + 32] = hn1;
            }
            if (t == TT - 1) {
                size_t gr = (size_t)(b0 + fi) * (3 * UU) + layer * UU + col0 + fj;
                g_R[gr]      = hn0;
                g_R[gr + 32] = hn1;
            }
        }

        // ---- arrive (release): publish h stores, bump group counter ----
        if (t < TT - 1) {
            __syncthreads();                  // all threads' stores done
            tgt += NSLC;
            if (tid == 0) {
                asm volatile("fence.acq_rel.gpu;" ::: "memory");
                atomicAdd(&g_bar[grp], 1u);
            }
        }
    }
}

__global__ void init_kernel() {
    int idx = blockIdx.x * blockDim.x + threadIdx.x;
    if (idx < 2 * BB * UU) ((float*)g_H)[idx] = 0.0f;
    if (idx < NGRP) g_bar[idx] = 0u;
}

__global__ void readout_kernel(const float* __restrict__ Wout,
                               const float* __restrict__ bout,
                               float* __restrict__ out) {
    __shared__ float red[NCLS][NT];
    int b = blockIdx.x, tid = threadIdx.x;
    float part[NCLS];
#pragma unroll
    for (int c = 0; c < NCLS; ++c) part[c] = 0.0f;
    for (int k = tid; k < 3 * UU; k += NT) {
        float r = g_R[(size_t)b * 3 * UU + k];
#pragma unroll
        for (int c = 0; c < NCLS; ++c) part[c] += r * Wout[k * NCLS + c];
    }
#pragma unroll
    for (int c = 0; c < NCLS; ++c) red[c][tid] = part[c];
    __syncthreads();
    if (tid < NCLS) {
        float s = 0.0f;
        for (int i = 0; i < NT; ++i) s += red[tid][i];
        out[b * NCLS + tid] = s + bout[tid];
    }
}

extern "C" void kernel_launch(void* const* d_in, const int* in_sizes, int n_in,
                              void* d_out, int out_size) {
    (void)in_sizes; (void)n_in; (void)out_size;
    const float* x    = (const float*)d_in[0];
    const float* Win0 = (const float*)d_in[1];
    const float* W0   = (const float*)d_in[2];
    const float* b0   = (const float*)d_in[3];
    const float* Win1 = (const float*)d_in[4];
    const float* W1   = (const float*)d_in[5];
    const float* b1   = (const float*)d_in[6];
    const float* Win2 = (const float*)d_in[7];
    const float* W2   = (const float*)d_in[8];
    const float* b2   = (const float*)d_in[9];
    const float* Wout = (const float*)d_in[10];
    const float* bout = (const float*)d_in[11];
    float* out = (float*)d_out;

    // smem: weights 64x516 + max(stage 16x516, red 16x16x66) = 199,680 B
    const int smem = (NCOL * SSTR + KCN * 16 * RSTR) * (int)sizeof(float);
    static int attr_done = 0;           // first call is uncaptured; replays skip
    if (!attr_done) {
        cudaFuncSetAttribute(recur_kernel,
                             cudaFuncAttributeMaxDynamicSharedMemorySize, smem);
        attr_done = 1;
    }

    const dim3 gemm_grid(UU / 64, (BB * TT) / 128);

    // layer 0
    init_kernel<<<1024, NT>>>();
    drive_gemm<<<gemm_grid, NT>>>(x, Win0, b0, 64, 0);
    recur_kernel<<<NGRP * NSLC, NTR, smem>>>(W0, 0);

    // layer 1
    init_kernel<<<1024, NT>>>();
    drive_gemm<<<gemm_grid, NT>>>(x, Win1, b1, 512, 1);
    recur_kernel<<<NGRP * NSLC, NTR, smem>>>(W1, 1);

    // layer 2
    init_kernel<<<1024, NT>>>();
    drive_gemm<<<gemm_grid, NT>>>(x, Win2, b2, 512, 2);
    recur_kernel<<<NGRP * NSLC, NTR, smem>>>(W2, 2);

    readout_kernel<<<BB, NT>>>(Wout, bout, out);
}

// round 11
// speedup vs baseline: 1.6396x; 1.0293x over previous
#include <cuda_runtime.h>

// ---------------------------------------------------------------------------
// DeepESN on B200 (sm_100a), round 11.
//   init (merged, up-front)  ->  [gemm0a, gemm0b, recur0, gemm1, recur1,
//                                 gemm2, recur2, readout]
//   drive GEMM: 128x128 tile, 8x8/thread, f32x2-packed, 2 CTAs/SM.
//   recurrence: 128 CTAs = 16 batch-groups (16 rows) x 8 col-slices (64 cols)
//     512 threads = 16 warps = 2 rowgroups x 8 k-chunks of 64
//     acc 8x2 f32x2 (32 regs - no spill), de-aliased reduction buffer,
//     own-slice h kept in SMEM across steps (skips 1/8 of staging + its
//     barrier dependency). Monotonic atomic barrier per group.
// ---------------------------------------------------------------------------

#define BB   256
#define TT   512
#define UU   512
#define NCLS 10

// recurrence tiling
#define NGRP 16
#define BCR  16
#define NSLC 8
#define NCOL 64
#define SSTR 516       // padded k stride
#define RSTR 66        // reduction slot stride
#define NTR  512
#define NT   256

// drive GEMM tiling (128x128, k-tile 8)
#define AST2 132
#define BST2 132

__device__ float        g_S0[(size_t)BB * TT * UU];
__device__ float        g_S1[(size_t)BB * TT * UU];
__device__ float        g_U [(size_t)BB * TT * UU];
__device__ float        g_H[3][2][BB * UU];          // per-layer double buffer
__device__ float        g_R[BB * 3 * UU];
__device__ unsigned int g_bar[3][NGRP];              // per-layer barrier rows

__device__ __forceinline__ void dfma2(unsigned long long& d,
                                      unsigned long long a,
                                      unsigned long long b) {
    asm("fma.rn.f32x2 %0, %1, %2, %0;" : "+l"(d) : "l"(a), "l"(b));
}
__device__ __forceinline__ float dsum2(unsigned long long v) {
    float lo, hi;
    asm("mov.b64 {%0, %1}, %2;" : "=f"(lo), "=f"(hi) : "l"(v));
    return lo + hi;
}
__device__ __forceinline__ unsigned long long pk2(float x) {
    unsigned long long r;
    asm("mov.b64 %0, {%1, %1};" : "=l"(r) : "f"(x));
    return r;
}
__device__ __forceinline__ void upk2(unsigned long long v, float& lo, float& hi) {
    asm("mov.b64 {%0, %1}, %2;" : "=f"(lo), "=f"(hi) : "l"(v));
}

// ============================================================================
// Drive GEMM: g_U[M,512] = A[M,K] @ W[K,512] + bias.  Tile 128x128, 256 thr,
// thread = 8 rows (4 f32x2 pairs) x 8 cols. K-tile = 8, 2 CTAs/SM.
// ============================================================================
__global__ void __launch_bounds__(NT)
drive_gemm(const float* __restrict__ x, const float* __restrict__ W,
           const float* __restrict__ bias, int K, int layer, int n_base)
{
    __shared__ float As[8 * AST2];    // transposed: As[k][row]
    __shared__ float Bs[8 * BST2];    // Bs[k][col]

    const float* A = (layer == 0) ? x : ((layer == 1) ? g_S0 : g_S1);
    float*       C = g_U;

    const int tid = threadIdx.x;
    const int tx  = tid & 15;         // col group: cols tx*8 .. tx*8+7
    const int ty  = tid >> 4;         // row group: rows ty*8 .. ty*8+7
    const int m0  = blockIdx.y * 128;
    const int n0  = n_base + blockIdx.x * 128;

    const int arow = tid >> 1;        // A-stage row
    const int ahalf = tid & 1;        // A-stage k-half
    const int bk  = tid >> 5;         // B-stage k
    const int bc4 = tid & 31;         // B-stage col/4

    unsigned long long acc[4][8];
#pragma unroll
    for (int p = 0; p < 4; ++p)
#pragma unroll
        for (int c = 0; c < 8; ++c) acc[p][c] = 0ull;

    for (int kt = 0; kt < K; kt += 8) {
        {
            float4 va = __ldg(reinterpret_cast<const float4*>(
                                  A + (size_t)(m0 + arow) * K + kt + ahalf * 4));
            As[(ahalf * 4 + 0) * AST2 + arow] = va.x;
            As[(ahalf * 4 + 1) * AST2 + arow] = va.y;
            As[(ahalf * 4 + 2) * AST2 + arow] = va.z;
            As[(ahalf * 4 + 3) * AST2 + arow] = va.w;
            float4 vb = __ldg(reinterpret_cast<const float4*>(
                                  W + (size_t)(kt + bk) * UU + n0 + bc4 * 4));
            *reinterpret_cast<float4*>(Bs + bk * BST2 + bc4 * 4) = vb;
        }
        __syncthreads();

#pragma unroll
        for (int k = 0; k < 8; ++k) {
            unsigned long long a[4];
#pragma unroll
            for (int p = 0; p < 4; ++p)
                a[p] = *reinterpret_cast<const unsigned long long*>(
                           As + k * AST2 + ty * 8 + 2 * p);
            float4 b0 = *reinterpret_cast<const float4*>(Bs + k * BST2 + tx * 8);
            float4 b1 = *reinterpret_cast<const float4*>(Bs + k * BST2 + tx * 8 + 4);
            unsigned long long bb[8] = {pk2(b0.x), pk2(b0.y), pk2(b0.z), pk2(b0.w),
                                        pk2(b1.x), pk2(b1.y), pk2(b1.z), pk2(b1.w)};
#pragma unroll
            for (int p = 0; p < 4; ++p)
#pragma unroll
                for (int c = 0; c < 8; ++c)
                    dfma2(acc[p][c], a[p], bb[c]);
        }
        __syncthreads();
    }

    float4 bv0 = __ldg(reinterpret_cast<const float4*>(bias + n0 + tx * 8));
    float4 bv1 = __ldg(reinterpret_cast<const float4*>(bias + n0 + tx * 8 + 4));
    const float bb[8] = {bv0.x, bv0.y, bv0.z, bv0.w, bv1.x, bv1.y, bv1.z, bv1.w};
#pragma unroll
    for (int p = 0; p < 4; ++p) {
        float lo[8], hi[8];
#pragma unroll
        for (int c = 0; c < 8; ++c) {
            upk2(acc[p][c], lo[c], hi[c]);
            lo[c] += bb[c]; hi[c] += bb[c];
        }
        size_t r0 = (size_t)(m0 + ty * 8 + 2 * p) * UU + n0 + tx * 8;
        *reinterpret_cast<float4*>(C + r0)          = make_float4(lo[0], lo[1], lo[2], lo[3]);
        *reinterpret_cast<float4*>(C + r0 + 4)      = make_float4(lo[4], lo[5], lo[6], lo[7]);
        *reinterpret_cast<float4*>(C + r0 + UU)     = make_float4(hi[0], hi[1], hi[2], hi[3]);
        *reinterpret_cast<float4*>(C + r0 + UU + 4) = make_float4(hi[4], hi[5], hi[6], hi[7]);
    }
}

// ============================================================================
// Recurrence. 16 warps = 2 rowgroups x 8 k-chunks of 64.
// Lane j: cols (col0+j, col0+j+32), rows rg*8..rg*8+7 (acc 8x2 f32x2).
// Own 64 cols of h are kept in sSt across steps (written at finalize).
// ============================================================================
__global__ void __launch_bounds__(NTR, 1)
recur_kernel(const float* __restrict__ Wrec, int layer)
{
    extern __shared__ float smem[];
    float* sWT  = smem;                       // [64][SSTR]
    float* sSt  = smem + NCOL * SSTR;         // [16][SSTR]
    float* sRed = sSt + BCR * SSTR;           // [8*16][RSTR]  (de-aliased)

    const float* u    = g_U;
    float*       sout = (layer == 0) ? g_S0 : ((layer == 1) ? g_S1 : (float*)0);
    float* const hbuf0 = g_H[layer][0];
    float* const hbuf1 = g_H[layer][1];
    unsigned int* const barp = &g_bar[layer][blockIdx.x >> 3];

    const int tid  = threadIdx.x;
    const int lane = tid & 31;
    const int wid  = tid >> 5;
    const int rg   = wid & 1;                 // rowgroup
    const int kc   = wid >> 1;                // k chunk [kc*64, kc*64+64)
    const int grp  = blockIdx.x >> 3;
    const int sl   = blockIdx.x & 7;
    const int b0   = grp * BCR;
    const int col0 = sl * NCOL;
    const int kbase = kc * 64;
    const int own0 = sl * 16;                 // own slice in float4 units
    (void)grp;

    const int fi = tid >> 5;                  // finalize row
    const int fj = lane;                      // finalize cols (fj, fj+32)

    for (int idx = tid; idx < NCOL * UU; idx += NTR) {
        int c = idx & 63, k = idx >> 6;
        sWT[c * SSTR + k] = Wrec[(size_t)k * UU + col0 + c];
    }
    __syncthreads();

    unsigned int tgt = 0;

    for (int t = 0; t < TT; ++t) {
        const int p = t & 1;
        const float* hsrc = p ? hbuf1 : hbuf0;
        float*       hdst = p ? hbuf0 : hbuf1;
        const size_t m = (size_t)(b0 + fi) * TT + t;

        const float u0 = __ldg(u + m * UU + col0 + fj);
        const float u1 = __ldg(u + m * UU + col0 + fj + 32);

        if (t > 0) {
            if (tid == 0) {
                unsigned int v;
                do {
                    asm volatile("ld.acquire.gpu.u32 %0, [%1];"
                                 : "=r"(v) : "l"(barp));
                    if (v >= tgt) break;
                    __nanosleep(32);
                } while (true);
            }
            __syncthreads();
        }

        // ---- stage foreign H cols (own 64 cols live in sSt already) ----
        if (t == 0) {
            for (int idx = tid; idx < BCR * 128; idx += NTR) {
                int i = idx >> 7, c = idx & 127;
                float4 v = __ldcg(reinterpret_cast<const float4*>(
                                      hsrc + (size_t)(b0 + i) * UU) + c);
                reinterpret_cast<float4*>(sSt + i * SSTR)[c] = v;
            }
        } else {
            for (int idx = tid; idx < BCR * 112; idx += NTR) {
                int i = idx / 112, c = idx - i * 112;
                int c4 = (c < own0) ? c : c + 16;
                float4 v = __ldcg(reinterpret_cast<const float4*>(
                                      hsrc + (size_t)(b0 + i) * UU) + c4);
                reinterpret_cast<float4*>(sSt + i * SSTR)[c4] = v;
            }
        }
        __syncthreads();

        // ---- matmul ----
        unsigned long long acc[8][2];
#pragma unroll
        for (int r = 0; r < 8; ++r) { acc[r][0] = 0ull; acc[r][1] = 0ull; }

        const ulonglong2* w0p = reinterpret_cast<const ulonglong2*>(
            sWT + lane * SSTR + kbase);
        const ulonglong2* w1p = reinterpret_cast<const ulonglong2*>(
            sWT + (lane + 32) * SSTR + kbase);
        const float* arow = sSt + rg * 8 * SSTR + kbase;

#pragma unroll 4
        for (int c = 0; c < 16; ++c) {
            ulonglong2 w0 = w0p[c];
            ulonglong2 w1 = w1p[c];
#pragma unroll
            for (int r = 0; r < 8; ++r) {
                ulonglong2 a = *reinterpret_cast<const ulonglong2*>(
                    arow + r * SSTR + 4 * c);
                dfma2(acc[r][0], a.x, w0.x);
                dfma2(acc[r][0], a.y, w0.y);
                dfma2(acc[r][1], a.x, w1.x);
                dfma2(acc[r][1], a.y, w1.y);
            }
        }

        // ---- partials: row = rg*8+r, plane kc; slot = lane*2 (+1) ----
        {
            float* base = sRed + (size_t)(kc * 16 + rg * 8) * RSTR + lane * 2;
#pragma unroll
            for (int r = 0; r < 8; ++r) {
                float2 v;
                v.x = dsum2(acc[r][0]);
                v.y = dsum2(acc[r][1]);
                *reinterpret_cast<float2*>(base + r * RSTR) = v;
            }
        }
        const float hold0 = sSt[fi * SSTR + col0 + fj];
        const float hold1 = sSt[fi * SSTR + col0 + fj + 32];
        __syncthreads();

        // ---- finalize ----
        {
            float z0 = u0, z1 = u1;
            const float* rb = sRed + (size_t)fi * RSTR + fj * 2;
#pragma unroll
            for (int k2 = 0; k2 < 8; ++k2) {
                float2 pv = *reinterpret_cast<const float2*>(
                    rb + (size_t)k2 * (16 * RSTR));
                z0 += pv.x; z1 += pv.y;
            }
            float hn0 = hold0 * 0.1f + 0.9f * tanhf(z0);
            float hn1 = hold1 * 0.1f + 0.9f * tanhf(z1);
            size_t gh = (size_t)(b0 + fi) * UU + col0 + fj;
            hdst[gh]      = hn0;                 // for the 7 peer CTAs
            hdst[gh + 32] = hn1;
            sSt[fi * SSTR + col0 + fj]      = hn0;   // own-slice carry
            sSt[fi * SSTR + col0 + fj + 32] = hn1;
            if (sout) {
                sout[m * UU + col0 + fj]      = hn0;
                sout[m * UU + col0 + fj + 32] = hn1;
            }
            if (t == TT - 1) {
                size_t gr = (size_t)(b0 + fi) * (3 * UU) + layer * UU + col0 + fj;
                g_R[gr]      = hn0;
                g_R[gr + 32] = hn1;
            }
        }

        if (t < TT - 1) {
            __syncthreads();
            tgt += NSLC;
            if (tid == 0) {
                asm volatile("fence.acq_rel.gpu;" ::: "memory");
                atomicAdd(barp, 1u);
            }
        }
    }
}

__global__ void init_kernel() {
    int idx = blockIdx.x * blockDim.x + threadIdx.x;
    if (idx < 3 * 2 * BB * UU) ((float*)g_H)[idx] = 0.0f;
    if (idx < 3 * NGRP) ((unsigned int*)g_bar)[idx] = 0u;
}

__global__ void readout_kernel(const float* __restrict__ Wout,
                               const float* __restrict__ bout,
                               float* __restrict__ out) {
    __shared__ float red[NCLS][NT];
    int b = blockIdx.x, tid = threadIdx.x;
    float part[NCLS];
#pragma unroll
    for (int c = 0; c < NCLS; ++c) part[c] = 0.0f;
    for (int k = tid; k < 3 * UU; k += NT) {
        float r = g_R[(size_t)b * 3 * UU + k];
#pragma unroll
        for (int c = 0; c < NCLS; ++c) part[c] += r * Wout[k * NCLS + c];
    }
#pragma unroll
    for (int c = 0; c < NCLS; ++c) red[c][tid] = part[c];
    __syncthreads();
    if (tid < NCLS) {
        float s = 0.0f;
        for (int i = 0; i < NT; ++i) s += red[tid][i];
        out[b * NCLS + tid] = s + bout[tid];
    }
}

extern "C" void kernel_launch(void* const* d_in, const int* in_sizes, int n_in,
                              void* d_out, int out_size) {
    (void)in_sizes; (void)n_in; (void)out_size;
    const float* x    = (const float*)d_in[0];
    const float* Win0 = (const float*)d_in[1];
    const float* W0   = (const float*)d_in[2];
    const float* b0   = (const float*)d_in[3];
    const float* Win1 = (const float*)d_in[4];
    const float* W1   = (const float*)d_in[5];
    const float* b1   = (const float*)d_in[6];
    const float* Win2 = (const float*)d_in[7];
    const float* W2   = (const float*)d_in[8];
    const float* b2   = (const float*)d_in[9];
    const float* Wout = (const float*)d_in[10];
    const float* bout = (const float*)d_in[11];
    float* out = (float*)d_out;

    // recur smem: 64x516 + 16x516 + 128x66 = 198,912 B
    const int smem = (NCOL * SSTR + BCR * SSTR + 128 * RSTR) * (int)sizeof(float);
    static int attr_done = 0;
    if (!attr_done) {
        cudaFuncSetAttribute(recur_kernel,
                             cudaFuncAttributeMaxDynamicSharedMemorySize, smem);
        attr_done = 1;
    }

    const dim3 ggrid(4, (BB * TT) / 128);        // full-width gemm
    const dim3 hgrid(2, (BB * TT) / 128);        // half-width gemm (layer 0 split)

    init_kernel<<<3072, NT>>>();                             // launch 1
    drive_gemm<<<hgrid, NT>>>(x, Win0, b0, 64, 0, 0);        // launch 2
    drive_gemm<<<hgrid, NT>>>(x, Win0, b0, 64, 0, 256);      // launch 3
    recur_kernel<<<NGRP * NSLC, NTR, smem>>>(W0, 0);         // launch 4 (ncu aim)
    drive_gemm<<<ggrid, NT>>>(x, Win1, b1, 512, 1, 0);
    recur_kernel<<<NGRP * NSLC, NTR, smem>>>(W1, 1);
    drive_gemm<<<ggrid, NT>>>(x, Win2, b2, 512, 2, 0);
    recur_kernel<<<NGRP * NSLC, NTR, smem>>>(W2, 2);
    readout_kernel<<<BB, NT>>>(Wout, bout, out);
}